// round 1
// baseline (speedup 1.0000x reference)
#include <cuda_runtime.h>
#include <math.h>

// Problem constants
#define NL   32768      // N*L tokens
#define HDIM 768
#define KFAC 256
#define NCH  3
#define MDIM 3072

// Scratch layout (floats):
//   [0,      S1)   : h  (LN1 out), later reused as y (LN2 out)
//   [S1,    2*S1)  : xr (attn out + residual)
//   [2*S1,  5*S1)  : qkv   [token, c, 3*KF]
//   [5*S1,  6*S1)  : ctx   [token, c, KF]
//   [2*S1,  6*S1)  : hid   [token, MDIM]  (reuses dead qkv+ctx region)
// S1 = NL*HDIM = 25165824 ; total = 6*S1 = 150994944 floats (604 MB)
__device__ float g_scratch[150994944];

// ---------------------------------------------------------------------------
// LayerNorm: one block (256 threads) per row of 768
// ---------------------------------------------------------------------------
__global__ void ln_kernel(const float* __restrict__ X,
                          const float* __restrict__ gamma,
                          const float* __restrict__ beta,
                          float* __restrict__ O)
{
    __shared__ float s1[8], s2[8];
    int row = blockIdx.x, t = threadIdx.x;
    const float* xr = X + (size_t)row * HDIM;
    float v0 = xr[t], v1 = xr[t + 256], v2 = xr[t + 512];
    float s  = v0 + v1 + v2;
    float ss = v0 * v0 + v1 * v1 + v2 * v2;
    #pragma unroll
    for (int o = 16; o > 0; o >>= 1) {
        s  += __shfl_down_sync(0xffffffffu, s, o);
        ss += __shfl_down_sync(0xffffffffu, ss, o);
    }
    if ((t & 31) == 0) { s1[t >> 5] = s; s2[t >> 5] = ss; }
    __syncthreads();
    if (t < 32) {
        float a = (t < 8) ? s1[t] : 0.f;
        float b = (t < 8) ? s2[t] : 0.f;
        #pragma unroll
        for (int o = 4; o > 0; o >>= 1) {
            a += __shfl_down_sync(0xffffffffu, a, o);
            b += __shfl_down_sync(0xffffffffu, b, o);
        }
        if (t == 0) { s1[0] = a; s2[0] = b; }
    }
    __syncthreads();
    float mu   = s1[0] * (1.0f / HDIM);
    float var  = s2[0] * (1.0f / HDIM) - mu * mu;
    float rstd = rsqrtf(var + 1e-6f);
    float* orow = O + (size_t)row * HDIM;
    orow[t]       = (v0 - mu) * rstd * gamma[t]       + beta[t];
    orow[t + 256] = (v1 - mu) * rstd * gamma[t + 256] + beta[t + 256];
    orow[t + 512] = (v2 - mu) * rstd * gamma[t + 512] + beta[t + 512];
}

// ---------------------------------------------------------------------------
// Criss-cross attention core: per (token, kf) a 3x3 score/softmax/context.
// qkv: [token][c][3*KF] ; ctx: [token][d(channel)][KF]
// ---------------------------------------------------------------------------
__global__ void attn_kernel(const float* __restrict__ qkv, float* __restrict__ ctx)
{
    long i = (long)blockIdx.x * blockDim.x + threadIdx.x;   // NL*KF threads
    int  kf    = (int)(i & (KFAC - 1));
    long token = i >> 8;
    const float* base = qkv + token * (NCH * 3 * KFAC);
    float q[3], k[3], v[3];
    #pragma unroll
    for (int c = 0; c < 3; c++) {
        q[c] = base[c * 768 + kf];
        k[c] = base[c * 768 + 256 + kf];
        v[c] = base[c * 768 + 512 + kf];
    }
    float o0 = 0.f, o1 = 0.f, o2 = 0.f;
    const float sc = 0.0625f;   // 1/sqrt(256)
    #pragma unroll
    for (int c = 0; c < 3; c++) {
        float s0 = q[c] * k[0] * sc;
        float s1 = q[c] * k[1] * sc;
        float s2 = q[c] * k[2] * sc;
        float m  = fmaxf(s0, fmaxf(s1, s2));
        float e0 = expf(s0 - m), e1 = expf(s1 - m), e2 = expf(s2 - m);
        float w  = v[c] / (e0 + e1 + e2);
        o0 = fmaf(e0, w, o0);
        o1 = fmaf(e1, w, o1);
        o2 = fmaf(e2, w, o2);
    }
    float* cb = ctx + token * (NCH * KFAC) + kf;
    cb[0]   = o0;
    cb[256] = o1;
    cb[512] = o2;
}

// ---------------------------------------------------------------------------
// Tiled SGEMM: C[b] = A[b] * B[b] + bias[b] (+ epilogue).
// 128x128x8 block tile, 256 threads, 8x8 per-thread micro-tile.
// EPI: 1 = +bias, 2 = +bias then exact GELU, 3 = +bias +residual R
// All problem dims divide the tile sizes (no bounds checks needed).
// ---------------------------------------------------------------------------
template<int EPI>
__global__ void __launch_bounds__(256, 2) sgemm_kernel(
    const float* __restrict__ A, int lda, long sA,
    const float* __restrict__ B, int ldb, long sB,
    float* __restrict__ C, int ldc, long sC,
    const float* __restrict__ bias, long sBias,
    const float* __restrict__ R,
    int M, int N, int K)
{
    __shared__ float As[8][132];
    __shared__ float Bs[8][132];

    int t  = threadIdx.x;
    int tx = t & 15, ty = t >> 4;
    int row0 = blockIdx.y * 128;
    int n0   = blockIdx.x * 128;
    long bz  = blockIdx.z;

    const float* Ab = A + bz * sA;
    const float* Bb = B + bz * sB;

    int arow = t >> 1,  acol = (t & 1) * 4;
    int brow = t >> 5,  bcol = (t & 31) * 4;
    const float* Aptr = Ab + (size_t)(row0 + arow) * lda + acol;
    const float* Bptr = Bb + (size_t)brow * ldb + n0 + bcol;

    float acc[8][8];
    #pragma unroll
    for (int i = 0; i < 8; i++)
        #pragma unroll
        for (int j = 0; j < 8; j++) acc[i][j] = 0.f;

    for (int k0 = 0; k0 < K; k0 += 8) {
        float4 av = *(const float4*)(Aptr + k0);
        float4 bv = *(const float4*)(Bptr + (size_t)k0 * ldb);
        As[acol + 0][arow] = av.x;
        As[acol + 1][arow] = av.y;
        As[acol + 2][arow] = av.z;
        As[acol + 3][arow] = av.w;
        *(float4*)&Bs[brow][bcol] = bv;
        __syncthreads();
        #pragma unroll
        for (int kk = 0; kk < 8; kk++) {
            float4 a0 = *(const float4*)&As[kk][ty * 8];
            float4 a1 = *(const float4*)&As[kk][ty * 8 + 4];
            float4 b0 = *(const float4*)&Bs[kk][tx * 8];
            float4 b1 = *(const float4*)&Bs[kk][tx * 8 + 4];
            float ar[8] = {a0.x, a0.y, a0.z, a0.w, a1.x, a1.y, a1.z, a1.w};
            float br[8] = {b0.x, b0.y, b0.z, b0.w, b1.x, b1.y, b1.z, b1.w};
            #pragma unroll
            for (int i = 0; i < 8; i++)
                #pragma unroll
                for (int j = 0; j < 8; j++)
                    acc[i][j] = fmaf(ar[i], br[j], acc[i][j]);
        }
        __syncthreads();
    }

    float* Cb = C + bz * sC;
    const float* biasb = bias + bz * sBias;
    #pragma unroll
    for (int i = 0; i < 8; i++) {
        int r = row0 + ty * 8 + i;
        float*       crow = Cb + (size_t)r * ldc + n0 + tx * 8;
        const float* rrow = (EPI == 3) ? (R + (size_t)r * ldc + n0 + tx * 8) : nullptr;
        #pragma unroll
        for (int j = 0; j < 8; j++) {
            float v = acc[i][j] + biasb[n0 + tx * 8 + j];
            if (EPI == 2) v = 0.5f * v * (1.0f + erff(v * 0.70710678118654752f));
            if (EPI == 3) v += rrow[j];
            crow[j] = v;
        }
    }
}

// ---------------------------------------------------------------------------
// Launch
// ---------------------------------------------------------------------------
extern "C" void kernel_launch(void* const* d_in, const int* in_sizes, int n_in,
                              void* d_out, int out_size)
{
    const float* x      = (const float*)d_in[0];
    const float* W_qkv  = (const float*)d_in[1];   // [3,256,768]
    const float* b_qkv  = (const float*)d_in[2];   // [3,768]
    const float* W_out  = (const float*)d_in[3];   // [256,256]
    const float* b_out  = (const float*)d_in[4];   // [256]
    const float* ln1_g  = (const float*)d_in[5];
    const float* ln1_b  = (const float*)d_in[6];
    const float* ln2_g  = (const float*)d_in[7];
    const float* ln2_b  = (const float*)d_in[8];
    const float* W1     = (const float*)d_in[9];   // [768,3072]
    const float* b1     = (const float*)d_in[10];  // [3072]
    const float* W2     = (const float*)d_in[11];  // [3072,768]
    const float* b2     = (const float*)d_in[12];  // [768]
    float* out = (float*)d_out;

    float* scratch = nullptr;
    cudaGetSymbolAddress((void**)&scratch, g_scratch);
    const long S1 = (long)NL * HDIM;
    float* h   = scratch;            // LN1 out; later reused as LN2 out
    float* xr  = scratch + S1;
    float* qkv = scratch + 2 * S1;
    float* ctx = scratch + 5 * S1;
    float* hid = scratch + 2 * S1;   // aliases qkv+ctx (dead by then)

    // 1) LN1
    ln_kernel<<<NL, 256>>>(x, ln1_g, ln1_b, h);

    // 2) QKV per-channel GEMM: [32768,256] @ [256,768] (+b), batched over C=3
    sgemm_kernel<1><<<dim3(HDIM / 128, NL / 128, NCH), 256>>>(
        h, HDIM, (long)KFAC,
        W_qkv, 3 * KFAC, (long)KFAC * 3 * KFAC,
        qkv, NCH * 3 * KFAC, (long)3 * KFAC,
        b_qkv, (long)3 * KFAC, nullptr,
        NL, 3 * KFAC, KFAC);

    // 3) criss-cross softmax core (bandwidth-bound elementwise)
    attn_kernel<<<(NL * KFAC) / 256, 256>>>(qkv, ctx);

    // 4) out-proj + bias + residual x -> xr : [98304,256] @ [256,256]
    sgemm_kernel<3><<<dim3(KFAC / 128, (NL * NCH) / 128, 1), 256>>>(
        ctx, KFAC, 0L,
        W_out, KFAC, 0L,
        xr, KFAC, 0L,
        b_out, 0L, x,
        NL * NCH, KFAC, KFAC);

    // 5) LN2 (reuse h as y)
    ln_kernel<<<NL, 256>>>(xr, ln2_g, ln2_b, h);

    // 6) MLP up + GELU: [32768,768] @ [768,3072]
    sgemm_kernel<2><<<dim3(MDIM / 128, NL / 128, 1), 256>>>(
        h, HDIM, 0L,
        W1, MDIM, 0L,
        hid, MDIM, 0L,
        b1, 0L, nullptr,
        NL, MDIM, HDIM);

    // 7) MLP down + bias + residual xr -> out: [32768,3072] @ [3072,768]
    sgemm_kernel<3><<<dim3(HDIM / 128, NL / 128, 1), 256>>>(
        hid, MDIM, 0L,
        W2, HDIM, 0L,
        out, HDIM, 0L,
        b2, 0L, xr,
        NL, HDIM, MDIM);
}

// round 3
// speedup vs baseline: 1.8935x; 1.8935x over previous
#include <cuda_runtime.h>
#include <cuda_bf16.h>
#include <math.h>
#include <stdint.h>

#define NL   32768
#define HDIM 768
#define KFAC 256
#define NCH  3
#define MDIM 3072

// ---------------------------------------------------------------------------
// Scratch
// ---------------------------------------------------------------------------
static const long S_H    = (long)NL * HDIM;
static const long S_HID  = (long)NL * MDIM;
static const long W1T_SZ = (long)HDIM * MDIM;
static const long WQT_SZ = (long)NCH * HDIM * KFAC;
static const long WOT_SZ = (long)KFAC * KFAC;

__device__ __nv_bfloat16 g_bf16[363069440];
__device__ float         g_f32[100663296];

#define B_H_HI   0L
#define B_H_LO   (S_H)
#define B_CTX_HI (2*S_H)
#define B_CTX_LO (3*S_H)
#define B_Y_HI   (4*S_H)
#define B_Y_LO   (5*S_H)
#define B_HID_HI (6*S_H)
#define B_HID_LO (6*S_H + S_HID)
#define B_W1H    (6*S_H + 2*S_HID)
#define B_W1L    (B_W1H + W1T_SZ)
#define B_W2H    (B_W1L + W1T_SZ)
#define B_W2L    (B_W2H + W1T_SZ)
#define B_WQH    (B_W2L + W1T_SZ)
#define B_WQL    (B_WQH + WQT_SZ)
#define B_WOH    (B_WQL + WQT_SZ)
#define B_WOL    (B_WOH + WOT_SZ)
#define F_QKV 0L
#define F_XR  75497472L

// ---------------------------------------------------------------------------
// PTX helpers (baseline features only: cp.async / ldmatrix / mma.sync)
// ---------------------------------------------------------------------------
__device__ __forceinline__ uint32_t smem_u32(const void* p) {
    uint32_t a;
    asm("{ .reg .u64 t; cvta.to.shared.u64 t, %1; cvt.u32.u64 %0, t; }" : "=r"(a) : "l"(p));
    return a;
}
#define CP_ASYNC16(dst, src) \
    asm volatile("cp.async.cg.shared.global [%0], [%1], 16;" :: "r"(dst), "l"(src))
#define CP_COMMIT() asm volatile("cp.async.commit_group;" ::: "memory")
#define CP_WAIT1()  asm volatile("cp.async.wait_group 1;" ::: "memory")

#define LDSM4(r0, r1, r2, r3, a) \
    asm volatile("ldmatrix.sync.aligned.m8n8.x4.shared.b16 {%0,%1,%2,%3}, [%4];" \
        : "=r"(r0), "=r"(r1), "=r"(r2), "=r"(r3) : "r"(a))

#define MMA_BF16(c, a, b0, b1) \
    asm volatile("mma.sync.aligned.m16n8k16.row.col.f32.bf16.bf16.f32 " \
        "{%0,%1,%2,%3}, {%4,%5,%6,%7}, {%8,%9}, {%0,%1,%2,%3};" \
        : "+f"((c)[0]), "+f"((c)[1]), "+f"((c)[2]), "+f"((c)[3]) \
        : "r"((a)[0]), "r"((a)[1]), "r"((a)[2]), "r"((a)[3]), "r"(b0), "r"(b1))

// ---------------------------------------------------------------------------
// LayerNorm -> bf16 hi/lo
// ---------------------------------------------------------------------------
__global__ void ln_kernel(const float* __restrict__ X,
                          const float* __restrict__ gamma,
                          const float* __restrict__ beta,
                          __nv_bfloat16* __restrict__ Ohi,
                          __nv_bfloat16* __restrict__ Olo)
{
    __shared__ float s1[8], s2[8];
    int row = blockIdx.x, t = threadIdx.x;
    const float* xr = X + (size_t)row * HDIM;
    float v0 = xr[t], v1 = xr[t + 256], v2 = xr[t + 512];
    float s  = v0 + v1 + v2;
    float ss = v0 * v0 + v1 * v1 + v2 * v2;
    #pragma unroll
    for (int o = 16; o > 0; o >>= 1) {
        s  += __shfl_down_sync(0xffffffffu, s, o);
        ss += __shfl_down_sync(0xffffffffu, ss, o);
    }
    if ((t & 31) == 0) { s1[t >> 5] = s; s2[t >> 5] = ss; }
    __syncthreads();
    if (t < 32) {
        float a = (t < 8) ? s1[t] : 0.f;
        float b = (t < 8) ? s2[t] : 0.f;
        #pragma unroll
        for (int o = 4; o > 0; o >>= 1) {
            a += __shfl_down_sync(0xffffffffu, a, o);
            b += __shfl_down_sync(0xffffffffu, b, o);
        }
        if (t == 0) { s1[0] = a; s2[0] = b; }
    }
    __syncthreads();
    float mu   = s1[0] * (1.0f / HDIM);
    float var  = s2[0] * (1.0f / HDIM) - mu * mu;
    float rstd = rsqrtf(var + 1e-6f);
    size_t o = (size_t)row * HDIM;
    float vv[3] = {v0, v1, v2};
    #pragma unroll
    for (int j = 0; j < 3; j++) {
        int idx = t + j * 256;
        float y = (vv[j] - mu) * rstd * gamma[idx] + beta[idx];
        __nv_bfloat16 hi = __float2bfloat16(y);
        __nv_bfloat16 lo = __float2bfloat16(y - __bfloat162float(hi));
        Ohi[o + idx] = hi; Olo[o + idx] = lo;
    }
}

// ---------------------------------------------------------------------------
// Criss-cross attention core -> ctx hi/lo
// ---------------------------------------------------------------------------
__global__ void attn_kernel(const float* __restrict__ qkv,
                            __nv_bfloat16* __restrict__ Chi,
                            __nv_bfloat16* __restrict__ Clo)
{
    long i = (long)blockIdx.x * blockDim.x + threadIdx.x;
    int  kf    = (int)(i & (KFAC - 1));
    long token = i >> 8;
    const float* base = qkv + token * (NCH * 3 * KFAC);
    float q[3], k[3], v[3];
    #pragma unroll
    for (int c = 0; c < 3; c++) {
        q[c] = base[c * 768 + kf];
        k[c] = base[c * 768 + 256 + kf];
        v[c] = base[c * 768 + 512 + kf];
    }
    float o0 = 0.f, o1 = 0.f, o2 = 0.f;
    const float sc = 0.0625f;
    #pragma unroll
    for (int c = 0; c < 3; c++) {
        float s0 = q[c] * k[0] * sc;
        float s1 = q[c] * k[1] * sc;
        float s2 = q[c] * k[2] * sc;
        float m  = fmaxf(s0, fmaxf(s1, s2));
        float e0 = expf(s0 - m), e1 = expf(s1 - m), e2 = expf(s2 - m);
        float w  = v[c] / (e0 + e1 + e2);
        o0 = fmaf(e0, w, o0);
        o1 = fmaf(e1, w, o1);
        o2 = fmaf(e2, w, o2);
    }
    long rb = token * (NCH * KFAC) + kf;
    float o[3] = {o0, o1, o2};
    #pragma unroll
    for (int d = 0; d < 3; d++) {
        __nv_bfloat16 hi = __float2bfloat16(o[d]);
        __nv_bfloat16 lo = __float2bfloat16(o[d] - __bfloat162float(hi));
        Chi[rb + d * 256] = hi; Clo[rb + d * 256] = lo;
    }
}

// ---------------------------------------------------------------------------
// Weight transpose + hi/lo split:  W [K, N] fp32  ->  T [N, K] bf16 hi/lo
// ---------------------------------------------------------------------------
__global__ void wprep_kernel(const float* __restrict__ W, long sW, int K, int N,
                             __nv_bfloat16* __restrict__ Th,
                             __nv_bfloat16* __restrict__ Tl, long sT)
{
    __shared__ float tile[32][33];
    const float* Wb = W + (long)blockIdx.z * sW;
    int k0 = blockIdx.x * 32, n0 = blockIdx.y * 32;
    int tx = threadIdx.x, ty = threadIdx.y;
    #pragma unroll
    for (int i = 0; i < 32; i += 8)
        tile[ty + i][tx] = Wb[(size_t)(k0 + ty + i) * N + n0 + tx];
    __syncthreads();
    #pragma unroll
    for (int i = 0; i < 32; i += 8) {
        float v = tile[tx][ty + i];
        __nv_bfloat16 hi = __float2bfloat16(v);
        __nv_bfloat16 lo = __float2bfloat16(v - __bfloat162float(hi));
        size_t o = (size_t)blockIdx.z * sT + (size_t)(n0 + ty + i) * K + (k0 + tx);
        Th[o] = hi; Tl[o] = lo;
    }
}

// ---------------------------------------------------------------------------
// HMMA GEMM: CTA tile 128x128, K-chunk 32, 8 warps (warp tile 64x32),
// 3-stage cp.async pipeline, bf16 hi/lo 3-pass accumulation.
// A: [M][lda] K-major hi/lo ; B: [N][ldb] K-major hi/lo (i.e. B^T)
// EPI: 0 = +bias -> fp32 ; 1 = +bias+residual -> fp32 ; 2 = +bias+GELU -> bf16 hi/lo
// ---------------------------------------------------------------------------
#define ROWB   80          // padded row pitch in bytes (32 bf16 data + 16B pad)
#define T_AH   0
#define T_AL   10240
#define T_BH   20480
#define T_BL   30720
#define STAGE  40960
#define NSTAGE 3
#define GEMM_SMEM (NSTAGE * STAGE)

__device__ __forceinline__ void load_stage(
    const __nv_bfloat16* __restrict__ Ah, const __nv_bfloat16* __restrict__ Al, long lda,
    const __nv_bfloat16* __restrict__ Bh, const __nv_bfloat16* __restrict__ Bl, long ldb,
    long kc, uint32_t sbase, int t)
{
    int row = t >> 1;
    int ce  = (t & 1) * 16;                 // element col offset
    uint32_t so = (uint32_t)row * ROWB + (t & 1) * 32;
    const __nv_bfloat16* pah = Ah + (long)row * lda + kc + ce;
    const __nv_bfloat16* pal = Al + (long)row * lda + kc + ce;
    const __nv_bfloat16* pbh = Bh + (long)row * ldb + kc + ce;
    const __nv_bfloat16* pbl = Bl + (long)row * ldb + kc + ce;
    CP_ASYNC16(sbase + T_AH + so,      pah);
    CP_ASYNC16(sbase + T_AH + so + 16, pah + 8);
    CP_ASYNC16(sbase + T_AL + so,      pal);
    CP_ASYNC16(sbase + T_AL + so + 16, pal + 8);
    CP_ASYNC16(sbase + T_BH + so,      pbh);
    CP_ASYNC16(sbase + T_BH + so + 16, pbh + 8);
    CP_ASYNC16(sbase + T_BL + so,      pbl);
    CP_ASYNC16(sbase + T_BL + so + 16, pbl + 8);
}

template<int EPI>
__global__ void __launch_bounds__(256, 1) gemm_mma(
    const __nv_bfloat16* __restrict__ Ah, const __nv_bfloat16* __restrict__ Al,
    int lda, long strideA,
    const __nv_bfloat16* __restrict__ Bh, const __nv_bfloat16* __restrict__ Bl,
    int ldb, long strideB,
    float* __restrict__ Cf, __nv_bfloat16* __restrict__ Ch, __nv_bfloat16* __restrict__ Cl,
    int ldc, long strideC,
    const float* __restrict__ bias, long strideBias,
    const float* __restrict__ R,
    int K)
{
    extern __shared__ __align__(128) char smem[];
    uint32_t sb = smem_u32(smem);
    int t = threadIdx.x, lane = t & 31, wid = t >> 5;
    int warp_m = wid >> 2, warp_n = wid & 3;          // 2 x 4 warps
    long m0 = (long)blockIdx.y * 128;
    int  n0 = blockIdx.x * 128;
    long z  = blockIdx.z;

    const __nv_bfloat16* Ahp = Ah + z * strideA + m0 * lda;
    const __nv_bfloat16* Alp = Al + z * strideA + m0 * lda;
    const __nv_bfloat16* Bhp = Bh + z * strideB + (long)n0 * ldb;
    const __nv_bfloat16* Blp = Bl + z * strideB + (long)n0 * ldb;

    float acc[4][4][4];
    #pragma unroll
    for (int i = 0; i < 4; i++)
        #pragma unroll
        for (int j = 0; j < 4; j++)
            #pragma unroll
            for (int k = 0; k < 4; k++) acc[i][j][k] = 0.f;

    const int KT = K >> 5;

    // prologue: stages 0,1
    load_stage(Ahp, Alp, lda, Bhp, Blp, ldb, 0, sb, t);
    CP_COMMIT();
    load_stage(Ahp, Alp, lda, Bhp, Blp, ldb, 32, sb + STAGE, t);
    CP_COMMIT();

    // per-lane ldmatrix offsets
    uint32_t lm = (uint32_t)(lane & 15) * ROWB + (lane >> 4) * 16;
    uint32_t aoff = (uint32_t)(warp_m * 64) * ROWB + lm;
    uint32_t boff = (uint32_t)T_BH + (uint32_t)(warp_n * 32) * ROWB + lm;

    for (int kt = 0; kt < KT; kt++) {
        CP_WAIT1();
        __syncthreads();
        if (kt + 2 < KT)
            load_stage(Ahp, Alp, lda, Bhp, Blp, ldb, (long)(kt + 2) << 5,
                       sb + (uint32_t)((kt + 2) % NSTAGE) * STAGE, t);
        CP_COMMIT();

        uint32_t stg = sb + (uint32_t)(kt % NSTAGE) * STAGE;
        #pragma unroll
        for (int kh = 0; kh < 2; kh++) {
            uint32_t ka = stg + aoff + kh * 32;
            uint32_t kb = stg + boff + kh * 32;
            uint32_t ah[4][4], al[4][4], bh[2][4], bl[2][4];
            #pragma unroll
            for (int tm = 0; tm < 4; tm++)
                LDSM4(ah[tm][0], ah[tm][1], ah[tm][2], ah[tm][3], ka + tm * (16 * ROWB));
            #pragma unroll
            for (int tm = 0; tm < 4; tm++)
                LDSM4(al[tm][0], al[tm][1], al[tm][2], al[tm][3], ka + T_AL + tm * (16 * ROWB));
            #pragma unroll
            for (int pn = 0; pn < 2; pn++)
                LDSM4(bh[pn][0], bh[pn][1], bh[pn][2], bh[pn][3], kb + pn * (16 * ROWB));
            #pragma unroll
            for (int pn = 0; pn < 2; pn++)
                LDSM4(bl[pn][0], bl[pn][1], bl[pn][2], bl[pn][3], kb + (T_BL - T_BH) + pn * (16 * ROWB));
            // pass 1: hi*hi
            #pragma unroll
            for (int tm = 0; tm < 4; tm++)
                #pragma unroll
                for (int tn = 0; tn < 4; tn++)
                    MMA_BF16(acc[tm][tn], ah[tm], bh[tn >> 1][tn & 1], bh[tn >> 1][(tn & 1) + 2]);
            // pass 2: lo*hi
            #pragma unroll
            for (int tm = 0; tm < 4; tm++)
                #pragma unroll
                for (int tn = 0; tn < 4; tn++)
                    MMA_BF16(acc[tm][tn], al[tm], bh[tn >> 1][tn & 1], bh[tn >> 1][(tn & 1) + 2]);
            // pass 3: hi*lo
            #pragma unroll
            for (int tm = 0; tm < 4; tm++)
                #pragma unroll
                for (int tn = 0; tn < 4; tn++)
                    MMA_BF16(acc[tm][tn], ah[tm], bl[tn >> 1][tn & 1], bl[tn >> 1][(tn & 1) + 2]);
        }
        __syncthreads();
    }

    // epilogue
    const float* biasb = bias + z * strideBias;
    #pragma unroll
    for (int tm = 0; tm < 4; tm++) {
        #pragma unroll
        for (int tn = 0; tn < 4; tn++) {
            long r = m0 + warp_m * 64 + tm * 16 + (lane >> 2);
            int  c = n0 + warp_n * 32 + tn * 8 + (lane & 3) * 2;
            float b0 = biasb[c], b1 = biasb[c + 1];
            float v0 = acc[tm][tn][0] + b0, v1 = acc[tm][tn][1] + b1;
            float v2 = acc[tm][tn][2] + b0, v3 = acc[tm][tn][3] + b1;
            if (EPI == 0 || EPI == 1) {
                float* p0 = Cf + z * strideC + r * ldc + c;
                float* p1 = Cf + z * strideC + (r + 8) * ldc + c;
                if (EPI == 1) {
                    float2 r0 = *(const float2*)(R + r * ldc + c);
                    float2 r1 = *(const float2*)(R + (r + 8) * ldc + c);
                    v0 += r0.x; v1 += r0.y; v2 += r1.x; v3 += r1.y;
                }
                *(float2*)p0 = make_float2(v0, v1);
                *(float2*)p1 = make_float2(v2, v3);
            } else {
                float g0 = 0.5f * v0 * (1.0f + erff(v0 * 0.70710678118654752f));
                float g1 = 0.5f * v1 * (1.0f + erff(v1 * 0.70710678118654752f));
                float g2 = 0.5f * v2 * (1.0f + erff(v2 * 0.70710678118654752f));
                float g3 = 0.5f * v3 * (1.0f + erff(v3 * 0.70710678118654752f));
                __nv_bfloat16 h0 = __float2bfloat16(g0), h1 = __float2bfloat16(g1);
                __nv_bfloat16 h2 = __float2bfloat16(g2), h3 = __float2bfloat16(g3);
                __nv_bfloat162 hh0 = {h0, h1}, hh1 = {h2, h3};
                __nv_bfloat162 ll0 = {__float2bfloat16(g0 - __bfloat162float(h0)),
                                      __float2bfloat16(g1 - __bfloat162float(h1))};
                __nv_bfloat162 ll1 = {__float2bfloat16(g2 - __bfloat162float(h2)),
                                      __float2bfloat16(g3 - __bfloat162float(h3))};
                *(__nv_bfloat162*)(Ch + r * ldc + c)       = hh0;
                *(__nv_bfloat162*)(Ch + (r + 8) * ldc + c) = hh1;
                *(__nv_bfloat162*)(Cl + r * ldc + c)       = ll0;
                *(__nv_bfloat162*)(Cl + (r + 8) * ldc + c) = ll1;
            }
        }
    }
}

// ---------------------------------------------------------------------------
// Launch
// ---------------------------------------------------------------------------
extern "C" void kernel_launch(void* const* d_in, const int* in_sizes, int n_in,
                              void* d_out, int out_size)
{
    const float* x      = (const float*)d_in[0];
    const float* W_qkv  = (const float*)d_in[1];
    const float* b_qkv  = (const float*)d_in[2];
    const float* W_out  = (const float*)d_in[3];
    const float* b_out  = (const float*)d_in[4];
    const float* ln1_g  = (const float*)d_in[5];
    const float* ln1_b  = (const float*)d_in[6];
    const float* ln2_g  = (const float*)d_in[7];
    const float* ln2_b  = (const float*)d_in[8];
    const float* W1     = (const float*)d_in[9];
    const float* b1     = (const float*)d_in[10];
    const float* W2     = (const float*)d_in[11];
    const float* b2     = (const float*)d_in[12];
    float* out = (float*)d_out;

    __nv_bfloat16* bb = nullptr; float* ff = nullptr;
    cudaGetSymbolAddress((void**)&bb, g_bf16);
    cudaGetSymbolAddress((void**)&ff, g_f32);

    cudaFuncSetAttribute(gemm_mma<0>, cudaFuncAttributeMaxDynamicSharedMemorySize, GEMM_SMEM);
    cudaFuncSetAttribute(gemm_mma<1>, cudaFuncAttributeMaxDynamicSharedMemorySize, GEMM_SMEM);
    cudaFuncSetAttribute(gemm_mma<2>, cudaFuncAttributeMaxDynamicSharedMemorySize, GEMM_SMEM);

    dim3 tb(32, 8);
    wprep_kernel<<<dim3(HDIM / 32, MDIM / 32, 1), tb>>>(W1, 0, HDIM, MDIM, bb + B_W1H, bb + B_W1L, 0);
    wprep_kernel<<<dim3(MDIM / 32, HDIM / 32, 1), tb>>>(W2, 0, MDIM, HDIM, bb + B_W2H, bb + B_W2L, 0);
    wprep_kernel<<<dim3(KFAC / 32, KFAC / 32, 1), tb>>>(W_out, 0, KFAC, KFAC, bb + B_WOH, bb + B_WOL, 0);
    wprep_kernel<<<dim3(KFAC / 32, HDIM / 32, NCH), tb>>>(W_qkv, (long)KFAC * HDIM, KFAC, HDIM,
                                                          bb + B_WQH, bb + B_WQL, (long)HDIM * KFAC);
    // 1) LN1
    ln_kernel<<<NL, 256>>>(x, ln1_g, ln1_b, bb + B_H_HI, bb + B_H_LO);

    // 2) QKV per channel: [32768 x 768] = A[32768 x 256k] * B[768n x 256k]^T
    gemm_mma<0><<<dim3(HDIM / 128, NL / 128, NCH), 256, GEMM_SMEM>>>(
        bb + B_H_HI, bb + B_H_LO, HDIM, (long)KFAC,
        bb + B_WQH, bb + B_WQL, KFAC, (long)HDIM * KFAC,
        ff + F_QKV, nullptr, nullptr, NCH * HDIM, (long)HDIM,
        b_qkv, (long)HDIM, nullptr, KFAC);

    // 3) attention core
    attn_kernel<<<(NL * KFAC) / 256, 256>>>(ff + F_QKV, bb + B_CTX_HI, bb + B_CTX_LO);

    // 4) out-proj + bias + residual x -> xr
    gemm_mma<1><<<dim3(KFAC / 128, (NL * NCH) / 128, 1), 256, GEMM_SMEM>>>(
        bb + B_CTX_HI, bb + B_CTX_LO, KFAC, 0L,
        bb + B_WOH, bb + B_WOL, KFAC, 0L,
        ff + F_XR, nullptr, nullptr, KFAC, 0L,
        b_out, 0L, x, KFAC);

    // 5) LN2
    ln_kernel<<<NL, 256>>>(ff + F_XR, ln2_g, ln2_b, bb + B_Y_HI, bb + B_Y_LO);

    // 6) MLP up + GELU -> hid hi/lo
    gemm_mma<2><<<dim3(MDIM / 128, NL / 128, 1), 256, GEMM_SMEM>>>(
        bb + B_Y_HI, bb + B_Y_LO, HDIM, 0L,
        bb + B_W1H, bb + B_W1L, HDIM, 0L,
        nullptr, bb + B_HID_HI, bb + B_HID_LO, MDIM, 0L,
        b1, 0L, nullptr, HDIM);

    // 7) MLP down + bias + residual xr -> out
    gemm_mma<1><<<dim3(HDIM / 128, NL / 128, 1), 256, GEMM_SMEM>>>(
        bb + B_HID_HI, bb + B_HID_LO, MDIM, 0L,
        bb + B_W2H, bb + B_W2L, MDIM, 0L,
        out, nullptr, nullptr, HDIM, 0L,
        b2, 0L, ff + F_XR, MDIM);
}